// round 4
// baseline (speedup 1.0000x reference)
#include <cuda_runtime.h>
#include <cuda_bf16.h>
#include <mma.h>

using namespace nvcuda;

#define Bb 256
#define Dd 256
#define Tt 512
#define Hh 512
#define G4 2048
#define Mm (Tt*Bb)   // 131072

// ---------------- device scratch (no runtime allocation allowed) ----------------
__device__ __nv_bfloat16 g_xb[(size_t)Mm*Dd];        // xs as bf16, [t*B+b][d]
__device__ float         g_xg[(size_t)Mm*G4];        // x_gates fp32 (includes biases)
__device__ __nv_bfloat16 g_wih[(size_t)Dd*G4];       // W_ih^T bf16 [k][n]
__device__ __nv_bfloat16 g_whh[(size_t)Hh*G4];       // W_hh^T bf16 [k][n]
__device__ float         g_biasmat[16*G4];           // 16 identical rows of (b_ih+b_hh)
__device__ __nv_bfloat16 g_h[2][(size_t)Bb*Hh];      // double-buffered hidden state
__device__ float         g_plog[16*(size_t)Tt*Bb];   // partial logits per u-tile
__device__ unsigned int  g_ctr[8][32];               // per batch-group arrival counter (128B apart)

__device__ __forceinline__ float tanh_fast(float x) {
    float y; asm("tanh.approx.f32 %0, %1;" : "=f"(y) : "f"(x)); return y;
}
__device__ __forceinline__ float sigm(float x) { return 1.0f / (1.0f + __expf(-x)); }

__device__ __forceinline__ void cp16(void* dst, const void* src) {
    unsigned d = (unsigned)__cvta_generic_to_shared(dst);
    asm volatile("cp.async.cg.shared.global [%0], [%1], 16;" :: "r"(d), "l"(src));
}

// ---------------- init: zero h0 and counters ----------------
__global__ void k_init() {
    int i = blockIdx.x * blockDim.x + threadIdx.x;
    if (i < 8 * 32) ((unsigned*)g_ctr)[i] = 0u;
    if (i < Bb * Hh) g_h[0][i] = __float2bfloat16(0.0f);
}

// ---------------- weight converts (transpose to [k][n], bf16) ----------------
__global__ void k_convert(const float* __restrict__ Wih, const float* __restrict__ Whh,
                          const float* __restrict__ bih, const float* __restrict__ bhh) {
    int i = blockIdx.x * blockDim.x + threadIdx.x;
    if (i < Dd * G4) {
        int k = i / G4, n = i % G4;
        g_wih[i] = __float2bfloat16(Wih[(size_t)n * Dd + k]);
    }
    if (i < Hh * G4) {
        int k = i / G4, n = i % G4;
        g_whh[i] = __float2bfloat16(Whh[(size_t)n * Hh + k]);
    }
    if (i < 16 * G4) {
        int n = i % G4;
        g_biasmat[i] = bih[n] + bhh[n];
    }
}

// ---------------- transpose x (B,D,T) -> g_xb[(t*B+b)*D + d] bf16 ----------------
__global__ void k_transpose(const float* __restrict__ x) {
    __shared__ float tile[32][33];
    int b  = blockIdx.z;
    int d0 = blockIdx.y * 32, t0 = blockIdx.x * 32;
    int tx = threadIdx.x, ty = threadIdx.y;   // 32 x 8
    const float* src = x + ((size_t)b * Dd + d0) * Tt + t0;
    for (int r = ty; r < 32; r += 8)
        tile[r][tx] = src[(size_t)r * Tt + tx];
    __syncthreads();
    for (int r = ty; r < 32; r += 8)
        g_xb[((size_t)(t0 + r) * Bb + b) * Dd + d0 + tx] = __float2bfloat16(tile[tx][r]);
}

// ---------------- GEMM1: g_xg = g_xb (M x 256) @ g_wih (256 x 2048) + bias ----------------
// 128x128 tile, 256 threads, 2-stage cp.async pipeline over 4 k-chunks of 64
#define GA_LD 72
#define GB_LD 136
#define G1_SMEM (2*128*GA_LD*2 + 2*64*GB_LD*2)

__global__ void __launch_bounds__(256) k_gemm1() {
    extern __shared__ char smg[];
    __nv_bfloat16 (*As)[128][GA_LD] = (__nv_bfloat16(*)[128][GA_LD])smg;
    __nv_bfloat16 (*Bs)[64][GB_LD]  = (__nv_bfloat16(*)[64][GB_LD])(smg + 2*128*GA_LD*2);

    int m0 = blockIdx.x * 128, n0 = blockIdx.y * 128;
    int tid = threadIdx.x;
    int w = tid >> 5;
    int mw = (w >> 1) * 32, nw = (w & 1) * 64;

    // stage loader
    auto load_stage = [&](int c, int s) {
        int k0 = c * 64;
        #pragma unroll
        for (int p = 0; p < 4; p++) {
            int idx = tid + p * 256;
            int r = idx >> 3, cc = (idx & 7) * 8;
            cp16(&As[s][r][cc], &g_xb[(size_t)(m0 + r) * Dd + k0 + cc]);
        }
        #pragma unroll
        for (int p = 0; p < 4; p++) {
            int idx = tid + p * 256;
            int r = idx >> 4, cc = (idx & 15) * 8;
            cp16(&Bs[s][r][cc], &g_wih[(size_t)(k0 + r) * G4 + n0 + cc]);
        }
        asm volatile("cp.async.commit_group;" ::: "memory");
    };

    load_stage(0, 0);

    wmma::fragment<wmma::accumulator, 16, 16, 16, float> acc[2][4];
    #pragma unroll
    for (int i = 0; i < 2; i++)
        #pragma unroll
        for (int j = 0; j < 4; j++)
            wmma::load_matrix_sync(acc[i][j], &g_biasmat[n0 + nw + 16 * j], G4, wmma::mem_row_major);

    #pragma unroll
    for (int c = 0; c < 4; c++) {
        if (c < 3) load_stage(c + 1, (c + 1) & 1);
        if (c < 3) asm volatile("cp.async.wait_group 1;" ::: "memory");
        else       asm volatile("cp.async.wait_group 0;" ::: "memory");
        __syncthreads();
        int s = c & 1;
        #pragma unroll
        for (int kk = 0; kk < 64; kk += 16) {
            wmma::fragment<wmma::matrix_a, 16, 16, 16, __nv_bfloat16, wmma::row_major> af[2];
            wmma::fragment<wmma::matrix_b, 16, 16, 16, __nv_bfloat16, wmma::row_major> bf[4];
            #pragma unroll
            for (int i = 0; i < 2; i++)
                wmma::load_matrix_sync(af[i], &As[s][mw + 16 * i][kk], GA_LD);
            #pragma unroll
            for (int j = 0; j < 4; j++)
                wmma::load_matrix_sync(bf[j], &Bs[s][kk][nw + 16 * j], GB_LD);
            #pragma unroll
            for (int i = 0; i < 2; i++)
                #pragma unroll
                for (int j = 0; j < 4; j++)
                    wmma::mma_sync(acc[i][j], af[i], bf[j], acc[i][j]);
        }
        __syncthreads();
    }
    #pragma unroll
    for (int i = 0; i < 2; i++)
        #pragma unroll
        for (int j = 0; j < 4; j++)
            wmma::store_matrix_sync(&g_xg[(size_t)(m0 + mw + 16 * i) * G4 + n0 + nw + 16 * j],
                                    acc[i][j], G4, wmma::mem_row_major);
}

// ---------------- persistent LSTM recurrence ----------------
// grid = 128 CTAs: blockIdx = bt*16 + ut ; CTA owns batch rows [bt*32, +32), units [ut*32, +32)
// MMA starts from zero acc (no xg dependency); xg[t] prefetched into registers during step t-1.
#define BS_LD 136
#define AS_LD 520
#define GT_LD 132
#define DSMEM_BYTES (512*BS_LD*2 + 32*AS_LD*2 + 32*GT_LD*4)

__global__ void __launch_bounds__(128, 1) k_lstm(const float* __restrict__ Wmlp) {
    extern __shared__ char smem[];
    __nv_bfloat16* Bs = (__nv_bfloat16*)smem;                          // [512][BS_LD]
    __nv_bfloat16* As = (__nv_bfloat16*)(smem + 512 * BS_LD * 2);      // [32][AS_LD]
    float*         Gt = (float*)(smem + 512 * BS_LD * 2 + 32 * AS_LD * 2); // [32][GT_LD] raw gate sums
    __shared__ float Wm[32];

    int tid = threadIdx.x, w = tid >> 5;
    int ut = blockIdx.x & 15, bt = blockIdx.x >> 4;
    int u0 = ut * 32, b0 = bt * 32;
    int bh = (w >> 1) * 16, uh = (w & 1) * 16;
    unsigned* ctr = &g_ctr[bt][0];

    // preload W_hh slice into SMEM: Bs[k][g*32+uu] = W_hh[g*512+u0+uu][k]
    for (int idx = tid; idx < 512 * 16; idx += 128) {
        int k = idx >> 4;
        int col = (idx & 15) * 8;
        int g = col >> 5, uu = col & 31;
        *(uint4*)&Bs[k * BS_LD + col] = *(const uint4*)&g_whh[(size_t)k * G4 + g * 512 + u0 + uu];
    }
    if (tid < 32) Wm[tid] = Wmlp[u0 + tid];

    // per-thread element ownership for the cell phase: b = tid>>2, cols q*8..q*8+7
    int eb = tid >> 2, eq = tid & 3;

    float c_reg[8];
    #pragma unroll
    for (int e = 0; e < 8; e++) c_reg[e] = 0.0f;

    // prefetch xg for t=0 into registers (4 gates x 8 floats)
    float4 xr[4][2];
    {
        const float* xbase = g_xg + ((size_t)0 * Bb + b0 + eb) * G4 + u0 + eq * 8;
        #pragma unroll
        for (int g = 0; g < 4; g++) {
            xr[g][0] = __ldg((const float4*)(xbase + g * 512));
            xr[g][1] = __ldg((const float4*)(xbase + g * 512 + 4));
        }
    }

    __syncthreads();

    for (int t = 0; t < Tt; t++) {
        int cur = t & 1, nxt = cur ^ 1;

        // copy my h rows (32 x 512 bf16) from global (L2-coherent) into SMEM
        const __nv_bfloat16* hsrc = g_h[cur] + (size_t)b0 * Hh;
        for (int idx = tid; idx < 32 * 64; idx += 128) {
            int r = idx >> 6, c = (idx & 63) * 8;
            *(uint4*)&As[r * AS_LD + c] = __ldcg((const uint4*)&hsrc[(size_t)r * Hh + c]);
        }
        __syncthreads();

        // raw recurrent gate sums: acc = h @ W_hh^T (zero init, no memory dependency)
        wmma::fragment<wmma::accumulator, 16, 16, 16, float> acc[4];
        #pragma unroll
        for (int g = 0; g < 4; g++)
            wmma::fill_fragment(acc[g], 0.0f);

        for (int k0 = 0; k0 < 512; k0 += 16) {
            wmma::fragment<wmma::matrix_a, 16, 16, 16, __nv_bfloat16, wmma::row_major> af;
            wmma::load_matrix_sync(af, &As[bh * AS_LD + k0], AS_LD);
            #pragma unroll
            for (int g = 0; g < 4; g++) {
                wmma::fragment<wmma::matrix_b, 16, 16, 16, __nv_bfloat16, wmma::row_major> bf;
                wmma::load_matrix_sync(bf, &Bs[k0 * BS_LD + g * 32 + uh], BS_LD);
                wmma::mma_sync(acc[g], af, bf, acc[g]);
            }
        }

        // dump raw gate sums to SMEM (row-major: batch x 128 gate-cols)
        #pragma unroll
        for (int g = 0; g < 4; g++)
            wmma::store_matrix_sync(&Gt[bh * GT_LD + g * 32 + uh], acc[g], GT_LD, wmma::mem_row_major);
        __syncthreads();

        // elementwise cell: gates = Gt + xr (prefetched), fast tanh; write h + partial logit
        {
            const float* grow = &Gt[eb * GT_LD + eq * 8];
            const float* xf = (const float*)xr;
            __nv_bfloat16 tmp[8];
            float s = 0.0f;
            #pragma unroll
            for (int e = 0; e < 8; e++) {
                float gi = grow[0 * 32 + e] + xf[0 * 8 + e];
                float gf = grow[1 * 32 + e] + xf[1 * 8 + e];
                float gg = grow[2 * 32 + e] + xf[2 * 8 + e];
                float go = grow[3 * 32 + e] + xf[3 * 8 + e];
                float ig = sigm(gi);
                float fg = sigm(gf);
                float gv = tanh_fast(gg);
                float og = sigm(go);
                float cn = fg * c_reg[e] + ig * gv;
                c_reg[e] = cn;
                float hv = og * tanh_fast(cn);
                tmp[e] = __float2bfloat16(hv);
                s += hv * Wm[eq * 8 + e];
            }
            __stcg((uint4*)&g_h[nxt][(size_t)(b0 + eb) * Hh + u0 + eq * 8], *(uint4*)tmp);
            s += __shfl_down_sync(0xffffffffu, s, 2, 4);
            s += __shfl_down_sync(0xffffffffu, s, 1, 4);
            if (eq == 0) g_plog[((size_t)ut * Tt + t) * Bb + b0 + eb] = s;
        }

        // prefetch xg for t+1 (in flight across the barrier wait)
        if (t + 1 < Tt) {
            const float* xbase = g_xg + ((size_t)(t + 1) * Bb + b0 + eb) * G4 + u0 + eq * 8;
            #pragma unroll
            for (int g = 0; g < 4; g++) {
                xr[g][0] = __ldg((const float4*)(xbase + g * 512));
                xr[g][1] = __ldg((const float4*)(xbase + g * 512 + 4));
            }
        }

        // group barrier: 16 CTAs of this batch group (skip after last step)
        if (t + 1 < Tt) {
            __syncthreads();   // all h-stores of this CTA issued before the release below
            if (tid == 0) {
                asm volatile("red.release.gpu.global.add.u32 [%0], 1;" :: "l"(ctr) : "memory");
                unsigned tgt = 16u * (unsigned)(t + 1);
                unsigned v;
                do {
                    asm volatile("ld.acquire.gpu.global.u32 %0, [%1];" : "=r"(v) : "l"(ctr) : "memory");
                } while (v < tgt);
            }
            __syncthreads();
        }
    }
}

// ---------------- reduce partial logits -> sigmoid -> out (B, T) ----------------
__global__ void k_out(const float* __restrict__ bmlp, float* __restrict__ out) {
    int t = blockIdx.x, b = threadIdx.x;
    float s = bmlp[0];
    #pragma unroll
    for (int j = 0; j < 16; j++)
        s += g_plog[((size_t)j * Tt + t) * Bb + b];
    out[(size_t)b * Tt + t] = 1.0f / (1.0f + __expf(-s));
}

// ---------------- launch ----------------
extern "C" void kernel_launch(void* const* d_in, const int* in_sizes, int n_in,
                              void* d_out, int out_size) {
    const float* x    = (const float*)d_in[0];
    const float* Wih  = (const float*)d_in[1];
    const float* Whh  = (const float*)d_in[2];
    const float* bih  = (const float*)d_in[3];
    const float* bhh  = (const float*)d_in[4];
    const float* Wmlp = (const float*)d_in[5];
    const float* bmlp = (const float*)d_in[6];
    float* out = (float*)d_out;

    k_init<<<512, 256>>>();
    k_convert<<<4096, 256>>>(Wih, Whh, bih, bhh);
    k_transpose<<<dim3(Tt / 32, Dd / 32, Bb), dim3(32, 8)>>>(x);

    cudaFuncSetAttribute(k_gemm1, cudaFuncAttributeMaxDynamicSharedMemorySize, G1_SMEM);
    k_gemm1<<<dim3(Mm / 128, G4 / 128), 256, G1_SMEM>>>();

    cudaFuncSetAttribute(k_lstm, cudaFuncAttributeMaxDynamicSharedMemorySize, DSMEM_BYTES);
    k_lstm<<<128, 128, DSMEM_BYTES>>>(Wmlp);

    k_out<<<Tt, Bb>>>(bmlp, out);
}

// round 5
// speedup vs baseline: 1.2310x; 1.2310x over previous
#include <cuda_runtime.h>
#include <cuda_bf16.h>
#include <mma.h>

using namespace nvcuda;

#define Bb 256
#define Dd 256
#define Tt 512
#define Hh 512
#define G4 2048
#define Mm (Tt*Bb)   // 131072

// ---------------- device scratch (no runtime allocation allowed) ----------------
__device__ __nv_bfloat16 g_xb[(size_t)Mm*Dd];        // xs as bf16, [t*B+b][d]
__device__ float         g_xg[(size_t)Mm*G4];        // x_gates fp32 (includes biases)
__device__ __nv_bfloat16 g_wih[(size_t)Dd*G4];       // W_ih^T bf16 [k][n]
__device__ __nv_bfloat16 g_whh[(size_t)Hh*G4];       // W_hh^T bf16 [k][n]
__device__ float         g_biasmat[16*G4];           // 16 identical rows of (b_ih+b_hh)
__device__ __nv_bfloat16 g_h[2][(size_t)Bb*Hh];      // double-buffered hidden state
__device__ float         g_plog[16*(size_t)Tt*Bb];   // partial logits per u-tile
__device__ unsigned int  g_ctr[8][32];               // per batch-group arrival counter (128B apart)

__device__ __forceinline__ float tanh_fast(float x) {
    float y; asm("tanh.approx.f32 %0, %1;" : "=f"(y) : "f"(x)); return y;
}
__device__ __forceinline__ float sigm(float x) { return 1.0f / (1.0f + __expf(-x)); }

__device__ __forceinline__ void cp16(void* dst, const void* src) {
    unsigned d = (unsigned)__cvta_generic_to_shared(dst);
    asm volatile("cp.async.cg.shared.global [%0], [%1], 16;" :: "r"(d), "l"(src));
}

// ---------------- init: zero h0 and counters ----------------
__global__ void k_init() {
    int i = blockIdx.x * blockDim.x + threadIdx.x;
    if (i < 8 * 32) ((unsigned*)g_ctr)[i] = 0u;
    if (i < Bb * Hh) g_h[0][i] = __float2bfloat16(0.0f);
}

// ---------------- weight converts (transpose to [k][n], bf16) ----------------
__global__ void k_convert(const float* __restrict__ Wih, const float* __restrict__ Whh,
                          const float* __restrict__ bih, const float* __restrict__ bhh) {
    int i = blockIdx.x * blockDim.x + threadIdx.x;
    if (i < Dd * G4) {
        int k = i / G4, n = i % G4;
        g_wih[i] = __float2bfloat16(Wih[(size_t)n * Dd + k]);
    }
    if (i < Hh * G4) {
        int k = i / G4, n = i % G4;
        g_whh[i] = __float2bfloat16(Whh[(size_t)n * Hh + k]);
    }
    if (i < 16 * G4) {
        int n = i % G4;
        g_biasmat[i] = bih[n] + bhh[n];
    }
}

// ---------------- transpose x (B,D,T) -> g_xb[(t*B+b)*D + d] bf16 ----------------
__global__ void k_transpose(const float* __restrict__ x) {
    __shared__ float tile[32][33];
    int b  = blockIdx.z;
    int d0 = blockIdx.y * 32, t0 = blockIdx.x * 32;
    int tx = threadIdx.x, ty = threadIdx.y;   // 32 x 8
    const float* src = x + ((size_t)b * Dd + d0) * Tt + t0;
    for (int r = ty; r < 32; r += 8)
        tile[r][tx] = src[(size_t)r * Tt + tx];
    __syncthreads();
    for (int r = ty; r < 32; r += 8)
        g_xb[((size_t)(t0 + r) * Bb + b) * Dd + d0 + tx] = __float2bfloat16(tile[tx][r]);
}

// ---------------- GEMM1: g_xg = g_xb (M x 256) @ g_wih (256 x 2048) + bias ----------------
// 128x128 tile, 256 threads, 2-stage cp.async pipeline. N is the FASTEST grid dim so the
// 16 consecutive CTAs share one A tile (L2-resident) and B (1MB) stays L2-resident.
#define GA_LD 72
#define GB_LD 136
#define G1_SMEM (2*128*GA_LD*2 + 2*64*GB_LD*2)

__global__ void __launch_bounds__(256) k_gemm1() {
    extern __shared__ char smg[];
    __nv_bfloat16 (*As)[128][GA_LD] = (__nv_bfloat16(*)[128][GA_LD])smg;
    __nv_bfloat16 (*Bs)[64][GB_LD]  = (__nv_bfloat16(*)[64][GB_LD])(smg + 2*128*GA_LD*2);

    int n0 = blockIdx.x * 128, m0 = blockIdx.y * 128;   // n fastest -> A-tile reuse
    int tid = threadIdx.x;
    int w = tid >> 5;
    int mw = (w >> 1) * 32, nw = (w & 1) * 64;

    auto load_stage = [&](int c, int s) {
        int k0 = c * 64;
        #pragma unroll
        for (int p = 0; p < 4; p++) {
            int idx = tid + p * 256;
            int r = idx >> 3, cc = (idx & 7) * 8;
            cp16(&As[s][r][cc], &g_xb[(size_t)(m0 + r) * Dd + k0 + cc]);
        }
        #pragma unroll
        for (int p = 0; p < 4; p++) {
            int idx = tid + p * 256;
            int r = idx >> 4, cc = (idx & 15) * 8;
            cp16(&Bs[s][r][cc], &g_wih[(size_t)(k0 + r) * G4 + n0 + cc]);
        }
        asm volatile("cp.async.commit_group;" ::: "memory");
    };

    load_stage(0, 0);

    wmma::fragment<wmma::accumulator, 16, 16, 16, float> acc[2][4];
    #pragma unroll
    for (int i = 0; i < 2; i++)
        #pragma unroll
        for (int j = 0; j < 4; j++)
            wmma::load_matrix_sync(acc[i][j], &g_biasmat[n0 + nw + 16 * j], G4, wmma::mem_row_major);

    #pragma unroll
    for (int c = 0; c < 4; c++) {
        if (c < 3) load_stage(c + 1, (c + 1) & 1);
        if (c < 3) asm volatile("cp.async.wait_group 1;" ::: "memory");
        else       asm volatile("cp.async.wait_group 0;" ::: "memory");
        __syncthreads();
        int s = c & 1;
        #pragma unroll
        for (int kk = 0; kk < 64; kk += 16) {
            wmma::fragment<wmma::matrix_a, 16, 16, 16, __nv_bfloat16, wmma::row_major> af[2];
            wmma::fragment<wmma::matrix_b, 16, 16, 16, __nv_bfloat16, wmma::row_major> bf[4];
            #pragma unroll
            for (int i = 0; i < 2; i++)
                wmma::load_matrix_sync(af[i], &As[s][mw + 16 * i][kk], GA_LD);
            #pragma unroll
            for (int j = 0; j < 4; j++)
                wmma::load_matrix_sync(bf[j], &Bs[s][kk][nw + 16 * j], GB_LD);
            #pragma unroll
            for (int i = 0; i < 2; i++)
                #pragma unroll
                for (int j = 0; j < 4; j++)
                    wmma::mma_sync(acc[i][j], af[i], bf[j], acc[i][j]);
        }
        __syncthreads();
    }
    #pragma unroll
    for (int i = 0; i < 2; i++)
        #pragma unroll
        for (int j = 0; j < 4; j++)
            wmma::store_matrix_sync(&g_xg[(size_t)(m0 + mw + 16 * i) * G4 + n0 + nw + 16 * j],
                                    acc[i][j], G4, wmma::mem_row_major);
}

// ---------------- persistent LSTM recurrence ----------------
// grid = 128 CTAs: blockIdx = bt*16 + ut ; CTA owns batch rows [bt*32,+32), units [ut*32,+32)
// 256 threads = 8 warps (2/SMSP): warp w -> batch half (w&1), gate (w>>1); 16x32 output each.
#define BS_LD 136
#define AS_LD 520
#define GT_LD 132
#define DSMEM_BYTES (512*BS_LD*2 + 32*AS_LD*2 + 32*GT_LD*4)

__global__ void __launch_bounds__(256, 1) k_lstm(const float* __restrict__ Wmlp) {
    extern __shared__ char smem[];
    __nv_bfloat16* Bs = (__nv_bfloat16*)smem;                          // [512][BS_LD]
    __nv_bfloat16* As = (__nv_bfloat16*)(smem + 512 * BS_LD * 2);      // [32][AS_LD]
    float*         Gt = (float*)(smem + 512 * BS_LD * 2 + 32 * AS_LD * 2); // [32][GT_LD]
    __shared__ float Wm[32];

    int tid = threadIdx.x, w = tid >> 5;
    int ut = blockIdx.x & 15, bt = blockIdx.x >> 4;
    int u0 = ut * 32, b0 = bt * 32;
    int bh = (w & 1) * 16;        // batch half
    int cg = w >> 1;              // gate index 0..3 (32 gate-cols)
    unsigned* ctr = &g_ctr[bt][0];

    // preload W_hh slice into SMEM: Bs[k][g*32+uu] = W_hh[g*512+u0+uu][k]
    for (int idx = tid; idx < 512 * 16; idx += 256) {
        int k = idx >> 4;
        int col = (idx & 15) * 8;
        int g = col >> 5, uu = col & 31;
        *(uint4*)&Bs[k * BS_LD + col] = *(const uint4*)&g_whh[(size_t)k * G4 + g * 512 + u0 + uu];
    }
    if (tid < 32) Wm[tid] = Wmlp[u0 + tid];

    // elementwise ownership: batch row eb = tid>>3 (0..31), unit quad eq = tid&7 (4 units each)
    int eb = tid >> 3, eq = tid & 7;

    float c_reg[4];
    #pragma unroll
    for (int e = 0; e < 4; e++) c_reg[e] = 0.0f;

    // prefetch xg for t=0 into registers (4 gates x 4 floats)
    float4 xr[4];
    {
        const float* xbase = g_xg + ((size_t)0 * Bb + b0 + eb) * G4 + u0 + eq * 4;
        #pragma unroll
        for (int g = 0; g < 4; g++)
            xr[g] = __ldg((const float4*)(xbase + g * 512));
    }

    __syncthreads();

    for (int t = 0; t < Tt; t++) {
        int cur = t & 1, nxt = cur ^ 1;

        // copy my h rows (32 x 512 bf16) from global (L2-coherent) into SMEM
        const __nv_bfloat16* hsrc = g_h[cur] + (size_t)b0 * Hh;
        for (int idx = tid; idx < 32 * 64; idx += 256) {
            int r = idx >> 6, c = (idx & 63) * 8;
            *(uint4*)&As[r * AS_LD + c] = __ldcg((const uint4*)&hsrc[(size_t)r * Hh + c]);
        }
        __syncthreads();

        // raw recurrent gate sums: acc = h @ W_hh^T (zero init); warp: 16 batch x 32 cols of gate cg
        wmma::fragment<wmma::accumulator, 16, 16, 16, float> acc[2];
        wmma::fill_fragment(acc[0], 0.0f);
        wmma::fill_fragment(acc[1], 0.0f);

        #pragma unroll 4
        for (int k0 = 0; k0 < 512; k0 += 16) {
            wmma::fragment<wmma::matrix_a, 16, 16, 16, __nv_bfloat16, wmma::row_major> af;
            wmma::load_matrix_sync(af, &As[bh * AS_LD + k0], AS_LD);
            #pragma unroll
            for (int j = 0; j < 2; j++) {
                wmma::fragment<wmma::matrix_b, 16, 16, 16, __nv_bfloat16, wmma::row_major> bf;
                wmma::load_matrix_sync(bf, &Bs[k0 * BS_LD + cg * 32 + 16 * j], BS_LD);
                wmma::mma_sync(acc[j], af, bf, acc[j]);
            }
        }

        #pragma unroll
        for (int j = 0; j < 2; j++)
            wmma::store_matrix_sync(&Gt[bh * GT_LD + cg * 32 + 16 * j], acc[j], GT_LD, wmma::mem_row_major);
        __syncthreads();

        // elementwise cell: gates = Gt + xr (prefetched); write h + partial logit
        {
            const float* grow = &Gt[eb * GT_LD + eq * 4];
            const float* xf = (const float*)xr;
            __nv_bfloat16 tmp[4];
            float s = 0.0f;
            #pragma unroll
            for (int e = 0; e < 4; e++) {
                float gi = grow[0 * 32 + e] + xf[0 * 4 + e];
                float gf = grow[1 * 32 + e] + xf[1 * 4 + e];
                float gg = grow[2 * 32 + e] + xf[2 * 4 + e];
                float go = grow[3 * 32 + e] + xf[3 * 4 + e];
                float ig = sigm(gi);
                float fg = sigm(gf);
                float gv = tanh_fast(gg);
                float og = sigm(go);
                float cn = fg * c_reg[e] + ig * gv;
                c_reg[e] = cn;
                float hv = og * tanh_fast(cn);
                tmp[e] = __float2bfloat16(hv);
                s += hv * Wm[eq * 4 + e];
            }
            __stcg((uint2*)&g_h[nxt][(size_t)(b0 + eb) * Hh + u0 + eq * 4], *(uint2*)tmp);
            s += __shfl_down_sync(0xffffffffu, s, 4, 8);
            s += __shfl_down_sync(0xffffffffu, s, 2, 8);
            s += __shfl_down_sync(0xffffffffu, s, 1, 8);
            if (eq == 0) g_plog[((size_t)ut * Tt + t) * Bb + b0 + eb] = s;
        }

        // prefetch xg for t+1 (in flight across the barrier wait)
        if (t + 1 < Tt) {
            const float* xbase = g_xg + ((size_t)(t + 1) * Bb + b0 + eb) * G4 + u0 + eq * 4;
            #pragma unroll
            for (int g = 0; g < 4; g++)
                xr[g] = __ldg((const float4*)(xbase + g * 512));
        }

        // group barrier: 16 CTAs of this batch group (skip after last step)
        if (t + 1 < Tt) {
            __syncthreads();
            if (tid == 0) {
                asm volatile("red.release.gpu.global.add.u32 [%0], 1;" :: "l"(ctr) : "memory");
                unsigned tgt = 16u * (unsigned)(t + 1);
                unsigned v;
                do {
                    asm volatile("ld.acquire.gpu.global.u32 %0, [%1];" : "=r"(v) : "l"(ctr) : "memory");
                } while (v < tgt);
            }
            __syncthreads();
        }
    }
}

// ---------------- reduce partial logits -> sigmoid -> out (B, T) ----------------
__global__ void k_out(const float* __restrict__ bmlp, float* __restrict__ out) {
    int t = blockIdx.x, b = threadIdx.x;
    float s = bmlp[0];
    #pragma unroll
    for (int j = 0; j < 16; j++)
        s += g_plog[((size_t)j * Tt + t) * Bb + b];
    out[(size_t)b * Tt + t] = 1.0f / (1.0f + __expf(-s));
}

// ---------------- launch ----------------
extern "C" void kernel_launch(void* const* d_in, const int* in_sizes, int n_in,
                              void* d_out, int out_size) {
    const float* x    = (const float*)d_in[0];
    const float* Wih  = (const float*)d_in[1];
    const float* Whh  = (const float*)d_in[2];
    const float* bih  = (const float*)d_in[3];
    const float* bhh  = (const float*)d_in[4];
    const float* Wmlp = (const float*)d_in[5];
    const float* bmlp = (const float*)d_in[6];
    float* out = (float*)d_out;

    k_init<<<512, 256>>>();
    k_convert<<<4096, 256>>>(Wih, Whh, bih, bhh);
    k_transpose<<<dim3(Tt / 32, Dd / 32, Bb), dim3(32, 8)>>>(x);

    cudaFuncSetAttribute(k_gemm1, cudaFuncAttributeMaxDynamicSharedMemorySize, G1_SMEM);
    k_gemm1<<<dim3(G4 / 128, Mm / 128), 256, G1_SMEM>>>();   // n fastest

    cudaFuncSetAttribute(k_lstm, cudaFuncAttributeMaxDynamicSharedMemorySize, DSMEM_BYTES);
    k_lstm<<<128, 256, DSMEM_BYTES>>>(Wmlp);

    k_out<<<Tt, Bb>>>(bmlp, out);
}